// round 9
// baseline (speedup 1.0000x reference)
#include <cuda_runtime.h>
#include <cuda_fp16.h>
#include <cstdint>

#define BB 2
#define NN 2048
#define EE 256
#define HH 4
#define DK 64
#define QM 128     // q rows per CTA (flash)
#define BN 64      // keys per tile (flash)
#define NT (NN/BN) // 32 tiles

// scratch (no allocations allowed anywhere)
__device__ float    g_Q[BB*HH*NN*DK];   // tf32 bits, pre-scaled by 1/8
__device__ float    g_K[BB*HH*NN*DK];   // tf32 bits
__device__ float    g_V[BB*HH*NN*DK];   // tf32 bits
__device__ float    g_Hc[BB*NN*EE];
__device__ uint32_t g_adjp[BB*NN*(NN/32)];  // packed adjacency bits

__device__ __forceinline__ uint32_t to_tf32(float x) {
    uint32_t u;
    asm("cvt.rna.tf32.f32 %0, %1;" : "=r"(u) : "f"(x));
    return u;
}

__device__ __forceinline__ void mma_tf32(float* c, const uint32_t* a,
                                         uint32_t b0, uint32_t b1) {
    asm volatile(
        "mma.sync.aligned.m16n8k8.row.col.f32.tf32.tf32.f32 "
        "{%0,%1,%2,%3}, {%4,%5,%6,%7}, {%8,%9}, {%0,%1,%2,%3};\n"
        : "+f"(c[0]), "+f"(c[1]), "+f"(c[2]), "+f"(c[3])
        : "r"(a[0]), "r"(a[1]), "r"(a[2]), "r"(a[3]), "r"(b0), "r"(b1));
}

__device__ __forceinline__ void mma_f16(float* c, const uint32_t* a,
                                        uint32_t b0, uint32_t b1) {
    asm volatile(
        "mma.sync.aligned.m16n8k16.row.col.f32.f16.f16.f32 "
        "{%0,%1,%2,%3}, {%4,%5,%6,%7}, {%8,%9}, {%0,%1,%2,%3};\n"
        : "+f"(c[0]), "+f"(c[1]), "+f"(c[2]), "+f"(c[3])
        : "r"(a[0]), "r"(a[1]), "r"(a[2]), "r"(a[3]), "r"(b0), "r"(b1));
}

__device__ __forceinline__ void hilo_h(float v, __half& hi, __half& lo) {
    hi = __float2half_rn(v);
    lo = __float2half_rn(v - __half2float(hi));
}

__device__ __forceinline__ uint32_t smem_u32(const void* p) {
    return (uint32_t)__cvta_generic_to_shared(p);
}
__device__ __forceinline__ void cp16(uint32_t dst, const void* src) {
    asm volatile("cp.async.ca.shared.global [%0], [%1], 16;" :: "r"(dst), "l"(src));
}
__device__ __forceinline__ void cp4(uint32_t dst, const void* src) {
    asm volatile("cp.async.ca.shared.global [%0], [%1], 4;" :: "r"(dst), "l"(src));
}
#define CP_COMMIT() asm volatile("cp.async.commit_group;" ::: "memory")
#define CP_WAIT(N)  asm volatile("cp.async.wait_group %0;" :: "n"(N) : "memory")

// ===========================================================================
// Kernel 0: pack adjacency to bitmask. One warp packs 32 consecutive words.
// ===========================================================================
__global__ void pack_adj_kernel(const int* __restrict__ adj) {
    const int lane = threadIdx.x & 31;
    const size_t wbase = (size_t)((blockIdx.x * blockDim.x + threadIdx.x) >> 5) * 32;
    uint32_t mine = 0;
    #pragma unroll
    for (int j = 0; j < 32; j++) {
        int v = adj[(wbase + j) * 32 + lane];
        uint32_t m = __ballot_sync(0xffffffffu, v != 0);
        if (j == lane) mine = m;
    }
    g_adjp[wbase + lane] = mine;
}

// ===========================================================================
// Kernel 1: QKV projection, fp16-split 3xHMMA. grid = (64, 12), 128 threads.
// ===========================================================================
__global__ void __launch_bounds__(128) qkv_mma_kernel(const float* __restrict__ x,
                                                      const float* __restrict__ Wq,
                                                      const float* __restrict__ Wk,
                                                      const float* __restrict__ Wv) {
    __shared__ __half Xhi[64][40], Xlo[64][40];
    __shared__ __half Whi[64][40], Wlo[64][40];   // n-major: [e][k]

    const int mat = blockIdx.y >> 2;
    const int h   = blockIdx.y & 3;
    const float* W  = (mat == 0) ? Wq : (mat == 1 ? Wk : Wv);
    float* outp     = (mat == 0) ? g_Q : (mat == 1 ? g_K : g_V);
    const int m0  = blockIdx.x * 64;
    const int tid = threadIdx.x;
    const int wid = tid >> 5;
    const int lane = tid & 31;
    const int g = lane >> 2, t = lane & 3;
    const int row0 = wid * 16 + g, row1 = row0 + 8;

    float c[8][4] = {};

    for (int k0 = 0; k0 < EE; k0 += 32) {
        {
            const int xr = tid >> 1, xq = tid & 1;
            const float4* src = (const float4*)(x + (size_t)(m0 + xr) * EE + k0 + xq * 16);
            #pragma unroll
            for (int i = 0; i < 4; i++) {
                float4 v = src[i];
                __half h0, h1, h2, h3, l0, l1, l2, l3;
                hilo_h(v.x, h0, l0); hilo_h(v.y, h1, l1);
                hilo_h(v.z, h2, l2); hilo_h(v.w, h3, l3);
                int cb = xq * 16 + i * 4;
                *(__half2*)(&Xhi[xr][cb])     = __halves2half2(h0, h1);
                *(__half2*)(&Xhi[xr][cb + 2]) = __halves2half2(h2, h3);
                *(__half2*)(&Xlo[xr][cb])     = __halves2half2(l0, l1);
                *(__half2*)(&Xlo[xr][cb + 2]) = __halves2half2(l2, l3);
            }
        }
        {
            const int n0 = tid & 63, kh = tid >> 6;
            const float* src = W + (size_t)(h * EE + k0 + kh * 16) * DK + n0;
            #pragma unroll
            for (int j = 0; j < 8; j++) {
                float va = src[(2 * j) * DK];
                float vb = src[(2 * j + 1) * DK];
                __half ha, hb, la, lb;
                hilo_h(va, ha, la); hilo_h(vb, hb, lb);
                *(__half2*)(&Whi[n0][kh * 16 + 2 * j]) = __halves2half2(ha, hb);
                *(__half2*)(&Wlo[n0][kh * 16 + 2 * j]) = __halves2half2(la, lb);
            }
        }
        __syncthreads();

        #pragma unroll
        for (int kc = 0; kc < 32; kc += 16) {
            uint32_t ahi[4], alo[4];
            ahi[0] = *(const uint32_t*)(&Xhi[row0][kc + 2 * t]);
            ahi[1] = *(const uint32_t*)(&Xhi[row1][kc + 2 * t]);
            ahi[2] = *(const uint32_t*)(&Xhi[row0][kc + 8 + 2 * t]);
            ahi[3] = *(const uint32_t*)(&Xhi[row1][kc + 8 + 2 * t]);
            alo[0] = *(const uint32_t*)(&Xlo[row0][kc + 2 * t]);
            alo[1] = *(const uint32_t*)(&Xlo[row1][kc + 2 * t]);
            alo[2] = *(const uint32_t*)(&Xlo[row0][kc + 8 + 2 * t]);
            alo[3] = *(const uint32_t*)(&Xlo[row1][kc + 8 + 2 * t]);
            #pragma unroll
            for (int nf = 0; nf < 8; nf++) {
                uint32_t bh0 = *(const uint32_t*)(&Whi[nf * 8 + g][kc + 2 * t]);
                uint32_t bh1 = *(const uint32_t*)(&Whi[nf * 8 + g][kc + 8 + 2 * t]);
                uint32_t bl0 = *(const uint32_t*)(&Wlo[nf * 8 + g][kc + 2 * t]);
                uint32_t bl1 = *(const uint32_t*)(&Wlo[nf * 8 + g][kc + 8 + 2 * t]);
                mma_f16(c[nf], ahi, bh0, bh1);
                mma_f16(c[nf], ahi, bl0, bl1);
                mma_f16(c[nf], alo, bh0, bh1);
            }
        }
        __syncthreads();
    }

    const float sc = (mat == 0) ? 0.125f : 1.0f;
    {
        int m = m0 + row0;
        int b = m >> 11, n = m & (NN - 1);
        float* dst = outp + ((size_t)(b * HH + h) * NN + n) * DK;
        #pragma unroll
        for (int nf = 0; nf < 8; nf++) {
            float2 w = {__uint_as_float(to_tf32(c[nf][0] * sc)),
                        __uint_as_float(to_tf32(c[nf][1] * sc))};
            *(float2*)(dst + nf * 8 + 2 * t) = w;
        }
    }
    {
        int m = m0 + row1;
        int b = m >> 11, n = m & (NN - 1);
        float* dst = outp + ((size_t)(b * HH + h) * NN + n) * DK;
        #pragma unroll
        for (int nf = 0; nf < 8; nf++) {
            float2 w = {__uint_as_float(to_tf32(c[nf][2] * sc)),
                        __uint_as_float(to_tf32(c[nf][3] * sc))};
            *(float2*)(dst + nf * 8 + 2 * t) = w;
        }
    }
}

// ===========================================================================
// Kernel 2: flash attention, cp.async double-buffered.
// grid = (16, 8), 256 threads. Dynamic smem: Ks[2]|Vs[2]|adjm[2].
// ===========================================================================
#define KS_STRIDE 68
#define KBUF (BN * KS_STRIDE)           // floats per K/V buffer
#define FL_SMEM ((2 * KBUF * 2) * 4 + 2 * QM * 2 * 4)

__global__ void __launch_bounds__(256) flash_mma_kernel() {
    extern __shared__ float sm[];
    float* Ks = sm;                     // [2][BN][KS_STRIDE]
    float* Vs = Ks + 2 * KBUF;          // [2][BN][KS_STRIDE]
    uint32_t* adjm = (uint32_t*)(Vs + 2 * KBUF);  // [2][QM][2]

    const int tid = threadIdx.x;
    const int wid = tid >> 5;
    const int lane = tid & 31;
    const int g = lane >> 2;
    const int t = lane & 3;
    const int bh = blockIdx.y;
    const int b  = bh >> 2;
    const int h  = bh & 3;
    const int q0 = blockIdx.x * QM;

    const int row0 = wid * 16 + g;
    const int row1 = row0 + 8;

    // staging roles
    const int krow = tid >> 2, kq = tid & 3;
    const int arow = tid >> 1, ahalf = tid & 1;
    const float* Kg0 = g_K + ((size_t)bh * NN + krow) * DK + kq * 16;
    const float* Vg0 = g_V + ((size_t)bh * NN + krow) * DK + kq * 16;
    const uint32_t* adjp_base = g_adjp + ((size_t)b * NN + q0 + arow) * (NN / 32) + ahalf;
    const uint32_t ks_dst = smem_u32(&Ks[krow * KS_STRIDE + kq * 16]);
    const uint32_t vs_dst = smem_u32(&Vs[krow * KS_STRIDE + kq * 16]);
    const uint32_t ad_dst = smem_u32(&adjm[arow * 2 + ahalf]);

    // preload Q fragments
    uint32_t qa[8][4];
    {
        const float* Q0 = g_Q + ((size_t)bh * NN + q0 + row0) * DK;
        const float* Q1 = g_Q + ((size_t)bh * NN + q0 + row1) * DK;
        #pragma unroll
        for (int kc = 0; kc < 8; kc++) {
            qa[kc][0] = __float_as_uint(Q0[kc * 8 + t]);
            qa[kc][1] = __float_as_uint(Q1[kc * 8 + t]);
            qa[kc][2] = __float_as_uint(Q0[kc * 8 + t + 4]);
            qa[kc][3] = __float_as_uint(Q1[kc * 8 + t + 4]);
        }
    }

    float oacc[8][4] = {};
    float m0r = -1e30f, m1r = -1e30f, l0r = 0.f, l1r = 0.f;

    // prefetch tile 0 into buffer 0
    {
        const float* Kg = Kg0;
        const float* Vg = Vg0;
        #pragma unroll
        for (int i = 0; i < 4; i++) {
            cp16(ks_dst + i * 16, Kg + i * 4);
            cp16(vs_dst + i * 16, Vg + i * 4);
        }
        cp4(ad_dst, adjp_base);
        CP_COMMIT();
    }

    for (int tile = 0; tile < NT; tile++) {
        const int buf = tile & 1;
        const int nbuf = buf ^ 1;

        if (tile + 1 < NT) {
            const int c1 = (tile + 1) * BN;
            const float* Kg = Kg0 + (size_t)c1 * DK;
            const float* Vg = Vg0 + (size_t)c1 * DK;
            const uint32_t koff = nbuf * KBUF * 4;
            #pragma unroll
            for (int i = 0; i < 4; i++) {
                cp16(ks_dst + koff + i * 16, Kg + i * 4);
                cp16(vs_dst + koff + i * 16, Vg + i * 4);
            }
            cp4(ad_dst + nbuf * QM * 2 * 4, adjp_base + (size_t)(tile + 1) * 2);
            CP_COMMIT();
            CP_WAIT(1);
        } else {
            CP_WAIT(0);
        }
        __syncthreads();

        const float* Kb = Ks + buf * KBUF;
        const float* Vb = Vs + buf * KBUF;
        const uint32_t* ab = adjm + buf * QM * 2;

        // ---- S = Q K^T ----
        float sacc[8][4] = {};
        #pragma unroll
        for (int nf = 0; nf < 8; nf++) {
            #pragma unroll
            for (int kc = 0; kc < 8; kc++) {
                uint32_t b0 = __float_as_uint(Kb[(nf * 8 + g) * KS_STRIDE + kc * 8 + t]);
                uint32_t b1 = __float_as_uint(Kb[(nf * 8 + g) * KS_STRIDE + kc * 8 + t + 4]);
                mma_tf32(sacc[nf], qa[kc], b0, b1);
            }
        }

        // ---- masked online softmax ----
        uint32_t w0lo = ab[row0 * 2], w0hi = ab[row0 * 2 + 1];
        uint32_t w1lo = ab[row1 * 2], w1hi = ab[row1 * 2 + 1];
        float mx0 = -1e30f, mx1 = -1e30f;
        #pragma unroll
        for (int nf = 0; nf < 8; nf++) {
            int ca = nf * 8 + 2 * t, cb = ca + 1;
            uint32_t wr0 = (ca < 32) ? w0lo : w0hi;
            uint32_t wr1 = (ca < 32) ? w1lo : w1hi;
            int sa = ca & 31, sb = cb & 31;
            sacc[nf][0] = ((wr0 >> sa) & 1u) ? sacc[nf][0] : -1e38f;
            sacc[nf][1] = ((wr0 >> sb) & 1u) ? sacc[nf][1] : -1e38f;
            sacc[nf][2] = ((wr1 >> sa) & 1u) ? sacc[nf][2] : -1e38f;
            sacc[nf][3] = ((wr1 >> sb) & 1u) ? sacc[nf][3] : -1e38f;
            mx0 = fmaxf(mx0, fmaxf(sacc[nf][0], sacc[nf][1]));
            mx1 = fmaxf(mx1, fmaxf(sacc[nf][2], sacc[nf][3]));
        }
        mx0 = fmaxf(mx0, __shfl_xor_sync(0xffffffffu, mx0, 1));
        mx0 = fmaxf(mx0, __shfl_xor_sync(0xffffffffu, mx0, 2));
        mx1 = fmaxf(mx1, __shfl_xor_sync(0xffffffffu, mx1, 1));
        mx1 = fmaxf(mx1, __shfl_xor_sync(0xffffffffu, mx1, 2));
        float mn0 = fmaxf(m0r, mx0);
        float mn1 = fmaxf(m1r, mx1);
        float s0 = 0.f, s1 = 0.f;
        #pragma unroll
        for (int nf = 0; nf < 8; nf++) {
            float p0 = __expf(sacc[nf][0] - mn0);
            float p1 = __expf(sacc[nf][1] - mn0);
            float p2 = __expf(sacc[nf][2] - mn1);
            float p3 = __expf(sacc[nf][3] - mn1);
            s0 += p0 + p1;
            s1 += p2 + p3;
            sacc[nf][0] = __uint_as_float(to_tf32(p0));
            sacc[nf][1] = __uint_as_float(to_tf32(p1));
            sacc[nf][2] = __uint_as_float(to_tf32(p2));
            sacc[nf][3] = __uint_as_float(to_tf32(p3));
        }
        s0 += __shfl_xor_sync(0xffffffffu, s0, 1);
        s0 += __shfl_xor_sync(0xffffffffu, s0, 2);
        s1 += __shfl_xor_sync(0xffffffffu, s1, 1);
        s1 += __shfl_xor_sync(0xffffffffu, s1, 2);
        float cf0 = __expf(m0r - mn0);
        float cf1 = __expf(m1r - mn1);
        l0r = l0r * cf0 + s0;  m0r = mn0;
        l1r = l1r * cf1 + s1;  m1r = mn1;
        #pragma unroll
        for (int nf = 0; nf < 8; nf++) {
            oacc[nf][0] *= cf0; oacc[nf][1] *= cf0;
            oacc[nf][2] *= cf1; oacc[nf][3] *= cf1;
        }

        // ---- O += P V ----
        const int src0 = (lane & ~3) | (t >> 1);
        const int src2 = src0 + 2;
        #pragma unroll
        for (int kc = 0; kc < 8; kc++) {
            float v00 = __shfl_sync(0xffffffffu, sacc[kc][0], src0);
            float v01 = __shfl_sync(0xffffffffu, sacc[kc][1], src0);
            float v10 = __shfl_sync(0xffffffffu, sacc[kc][2], src0);
            float v11 = __shfl_sync(0xffffffffu, sacc[kc][3], src0);
            float v20 = __shfl_sync(0xffffffffu, sacc[kc][0], src2);
            float v21 = __shfl_sync(0xffffffffu, sacc[kc][1], src2);
            float v30 = __shfl_sync(0xffffffffu, sacc[kc][2], src2);
            float v31 = __shfl_sync(0xffffffffu, sacc[kc][3], src2);
            uint32_t pa[4];
            pa[0] = __float_as_uint((t & 1) ? v01 : v00);
            pa[1] = __float_as_uint((t & 1) ? v11 : v10);
            pa[2] = __float_as_uint((t & 1) ? v21 : v20);
            pa[3] = __float_as_uint((t & 1) ? v31 : v30);
            #pragma unroll
            for (int nf = 0; nf < 8; nf++) {
                uint32_t b0 = __float_as_uint(Vb[(kc * 8 + t) * KS_STRIDE + nf * 8 + g]);
                uint32_t b1 = __float_as_uint(Vb[(kc * 8 + t + 4) * KS_STRIDE + nf * 8 + g]);
                mma_tf32(oacc[nf], pa, b0, b1);
            }
        }
        __syncthreads();
    }

    // ---- epilogue ----
    float inv0 = (l0r > 0.f) ? 1.f / l0r : 0.f;
    float inv1 = (l1r > 0.f) ? 1.f / l1r : 0.f;
    float* d0 = g_Hc + ((size_t)(b * NN + q0 + row0)) * EE + h * DK;
    float* d1 = g_Hc + ((size_t)(b * NN + q0 + row1)) * EE + h * DK;
    #pragma unroll
    for (int nf = 0; nf < 8; nf++) {
        int c = nf * 8 + 2 * t;
        float2 w0 = {oacc[nf][0] * inv0, oacc[nf][1] * inv0};
        float2 w1 = {oacc[nf][2] * inv1, oacc[nf][3] * inv1};
        *(float2*)(d0 + c) = w0;
        *(float2*)(d1 + c) = w1;
    }
}

// ===========================================================================
// Kernel 3: out = Hc @ Wo^T + bo, fp16-split 3xHMMA.
// grid = (32, 4), 256 threads, 128-row tiles -> one wave.
// ===========================================================================
__global__ void __launch_bounds__(256) out_mma_kernel(const float* __restrict__ Wo,
                                                      const float* __restrict__ bo,
                                                      float* __restrict__ out) {
    __shared__ __half Xhi[128][40], Xlo[128][40];
    __shared__ __half Whi[64][40], Wlo[64][40];   // n-major: [n][k]

    const int m0 = blockIdx.x * 128;
    const int c0 = blockIdx.y * 64;
    const int tid = threadIdx.x;
    const int wid = tid >> 5;
    const int lane = tid & 31;
    const int g = lane >> 2, t = lane & 3;
    const int row0 = wid * 16 + g, row1 = row0 + 8;

    float c[8][4] = {};

    for (int k0 = 0; k0 < EE; k0 += 32) {
        {   // stage Hc [128 m x 32 k]
            const int xr = tid >> 1, xq = tid & 1;
            const float4* src = (const float4*)(g_Hc + (size_t)(m0 + xr) * EE + k0 + xq * 16);
            #pragma unroll
            for (int i = 0; i < 4; i++) {
                float4 v = src[i];
                __half h0, h1, h2, h3, l0, l1, l2, l3;
                hilo_h(v.x, h0, l0); hilo_h(v.y, h1, l1);
                hilo_h(v.z, h2, l2); hilo_h(v.w, h3, l3);
                int cb = xq * 16 + i * 4;
                *(__half2*)(&Xhi[xr][cb])     = __halves2half2(h0, h1);
                *(__half2*)(&Xhi[xr][cb + 2]) = __halves2half2(h2, h3);
                *(__half2*)(&Xlo[xr][cb])     = __halves2half2(l0, l1);
                *(__half2*)(&Xlo[xr][cb + 2]) = __halves2half2(l2, l3);
            }
        }
        {   // stage Wo [64 n x 32 k]
            const int nr = tid >> 2, nq = tid & 3;
            const float4* src = (const float4*)(Wo + (size_t)(c0 + nr) * EE + k0 + nq * 8);
            #pragma unroll
            for (int i = 0; i < 2; i++) {
                float4 v = src[i];
                __half h0, h1, h2, h3, l0, l1, l2, l3;
                hilo_h(v.x, h0, l0); hilo_h(v.y, h1, l1);
                hilo_h(v.z, h2, l2); hilo_h(v.w, h3, l3);
                int cb = nq * 8 + i * 4;
                *(__half2*)(&Whi[nr][cb])     = __halves2half2(h0, h1);
                *(__half2*)(&Whi[nr][cb + 2]) = __halves2half2(h2, h3);
                *(__half2*)(&Wlo[nr][cb])     = __halves2half2(l0, l1);
                *(__half2*)(&Wlo[nr][cb + 2]) = __halves2half2(l2, l3);
            }
        }
        __syncthreads();

        #pragma unroll
        for (int kc = 0; kc < 32; kc += 16) {
            uint32_t ahi[4], alo[4];
            ahi[0] = *(const uint32_t*)(&Xhi[row0][kc + 2 * t]);
            ahi[1] = *(const uint32_t*)(&Xhi[row1][kc + 2 * t]);
            ahi[2] = *(const uint32_t*)(&Xhi[row0][kc + 8 + 2 * t]);
            ahi[3] = *(const uint32_t*)(&Xhi[row1][kc + 8 + 2 * t]);
            alo[0] = *(const uint32_t*)(&Xlo[row0][kc + 2 * t]);
            alo[1] = *(const uint32_t*)(&Xlo[row1][kc + 2 * t]);
            alo[2] = *(const uint32_t*)(&Xlo[row0][kc + 8 + 2 * t]);
            alo[3] = *(const uint32_t*)(&Xlo[row1][kc + 8 + 2 * t]);
            #pragma unroll
            for (int nf = 0; nf < 8; nf++) {
                uint32_t bh0 = *(const uint32_t*)(&Whi[nf * 8 + g][kc + 2 * t]);
                uint32_t bh1 = *(const uint32_t*)(&Whi[nf * 8 + g][kc + 8 + 2 * t]);
                uint32_t bl0 = *(const uint32_t*)(&Wlo[nf * 8 + g][kc + 2 * t]);
                uint32_t bl1 = *(const uint32_t*)(&Wlo[nf * 8 + g][kc + 8 + 2 * t]);
                mma_f16(c[nf], ahi, bh0, bh1);
                mma_f16(c[nf], ahi, bl0, bl1);
                mma_f16(c[nf], alo, bh0, bh1);
            }
        }
        __syncthreads();
    }

    #pragma unroll
    for (int nf = 0; nf < 8; nf++) {
        int cc = c0 + nf * 8 + 2 * t;
        float b0v = bo[cc], b1v = bo[cc + 1];
        float2 w0 = {c[nf][0] + b0v, c[nf][1] + b1v};
        float2 w1 = {c[nf][2] + b0v, c[nf][3] + b1v};
        *(float2*)(out + (size_t)(m0 + row0) * EE + cc) = w0;
        *(float2*)(out + (size_t)(m0 + row1) * EE + cc) = w1;
    }
}

extern "C" void kernel_launch(void* const* d_in, const int* in_sizes, int n_in,
                              void* d_out, int out_size) {
    const float* x   = (const float*)d_in[0];
    const int*   adj = (const int*)  d_in[1];
    const float* Wq  = (const float*)d_in[2];
    const float* Wk  = (const float*)d_in[3];
    const float* Wv  = (const float*)d_in[4];
    const float* Wo  = (const float*)d_in[5];
    const float* bo  = (const float*)d_in[6];
    float* out = (float*)d_out;

    pack_adj_kernel<<<(BB * NN * (NN / 32)) / (8 * 32), 256>>>(adj);
    qkv_mma_kernel<<<dim3((BB * NN) / 64, 12), 128>>>(x, Wq, Wk, Wv);

    cudaFuncSetAttribute(flash_mma_kernel,
                         cudaFuncAttributeMaxDynamicSharedMemorySize, FL_SMEM);
    flash_mma_kernel<<<dim3(NN / QM, BB * HH), 256, FL_SMEM>>>();

    out_mma_kernel<<<dim3((BB * NN) / 128, EE / 64), 256>>>(Wo, bo, out);
}

// round 14
// speedup vs baseline: 1.6569x; 1.6569x over previous
#include <cuda_runtime.h>
#include <cuda_fp16.h>
#include <cstdint>

#define BB 2
#define NN 2048
#define EE 256
#define HH 4
#define DK 64
#define QM 128     // q rows per CTA (flash)
#define BN 64      // keys per tile (flash)
#define NT (NN/BN) // 32 tiles

// scratch (no allocations allowed anywhere)
__device__ __half   g_Qh[BB*HH*NN*DK];   // fp16, pre-scaled by 1/8
__device__ __half   g_Kh[BB*HH*NN*DK];   // fp16, [bh][n][d]
__device__ __half   g_Vt[BB*HH*DK*NN];   // fp16, TRANSPOSED [bh][d][n]
__device__ float    g_Hc[BB*NN*EE];
__device__ uint32_t g_adjp[BB*NN*(NN/32)];  // packed adjacency bits

__device__ __forceinline__ void mma_f16(float* c, const uint32_t* a,
                                        uint32_t b0, uint32_t b1) {
    asm volatile(
        "mma.sync.aligned.m16n8k16.row.col.f32.f16.f16.f32 "
        "{%0,%1,%2,%3}, {%4,%5,%6,%7}, {%8,%9}, {%0,%1,%2,%3};\n"
        : "+f"(c[0]), "+f"(c[1]), "+f"(c[2]), "+f"(c[3])
        : "r"(a[0]), "r"(a[1]), "r"(a[2]), "r"(a[3]), "r"(b0), "r"(b1));
}

__device__ __forceinline__ void hilo_h(float v, __half& hi, __half& lo) {
    hi = __float2half_rn(v);
    lo = __float2half_rn(v - __half2float(hi));
}

__device__ __forceinline__ uint32_t f22h(float a, float b) {
    __half2 h = __floats2half2_rn(a, b);
    return *(uint32_t*)&h;
}

__device__ __forceinline__ uint32_t smem_u32(const void* p) {
    return (uint32_t)__cvta_generic_to_shared(p);
}
__device__ __forceinline__ void cp16(uint32_t dst, const void* src) {
    asm volatile("cp.async.ca.shared.global [%0], [%1], 16;" :: "r"(dst), "l"(src));
}
__device__ __forceinline__ void cp4(uint32_t dst, const void* src) {
    asm volatile("cp.async.ca.shared.global [%0], [%1], 4;" :: "r"(dst), "l"(src));
}
#define CP_COMMIT() asm volatile("cp.async.commit_group;" ::: "memory")
#define CP_WAIT(N)  asm volatile("cp.async.wait_group %0;" :: "n"(N) : "memory")

// ===========================================================================
// Kernel 0: pack adjacency to bitmask.
// ===========================================================================
__global__ void pack_adj_kernel(const int* __restrict__ adj) {
    const int lane = threadIdx.x & 31;
    const size_t wbase = (size_t)((blockIdx.x * blockDim.x + threadIdx.x) >> 5) * 32;
    uint32_t mine = 0;
    #pragma unroll
    for (int j = 0; j < 32; j++) {
        int v = adj[(wbase + j) * 32 + lane];
        uint32_t m = __ballot_sync(0xffffffffu, v != 0);
        if (j == lane) mine = m;
    }
    g_adjp[wbase + lane] = mine;
}

// ===========================================================================
// Kernel 1: QKV projection, fp16-split 3xHMMA. grid = (64, 12), 128 threads.
// Q/K written as fp16 [bh][n][d]; V written fp16 TRANSPOSED [bh][d][n].
// ===========================================================================
__global__ void __launch_bounds__(128) qkv_mma_kernel(const float* __restrict__ x,
                                                      const float* __restrict__ Wq,
                                                      const float* __restrict__ Wk,
                                                      const float* __restrict__ Wv) {
    __shared__ __half Xhi[64][40], Xlo[64][40];
    __shared__ __half Whi[64][40], Wlo[64][40];   // n-major: [e][k]
    __shared__ __half Vsm[64 * 72];               // V transpose buffer [d][n]

    const int mat = blockIdx.y >> 2;
    const int h   = blockIdx.y & 3;
    const float* W = (mat == 0) ? Wq : (mat == 1 ? Wk : Wv);
    const int m0  = blockIdx.x * 64;
    const int tid = threadIdx.x;
    const int wid = tid >> 5;
    const int lane = tid & 31;
    const int g = lane >> 2, t = lane & 3;
    const int row0 = wid * 16 + g, row1 = row0 + 8;

    float c[8][4] = {};

    for (int k0 = 0; k0 < EE; k0 += 32) {
        {
            const int xr = tid >> 1, xq = tid & 1;
            const float4* src = (const float4*)(x + (size_t)(m0 + xr) * EE + k0 + xq * 16);
            #pragma unroll
            for (int i = 0; i < 4; i++) {
                float4 v = src[i];
                __half h0, h1, h2, h3, l0, l1, l2, l3;
                hilo_h(v.x, h0, l0); hilo_h(v.y, h1, l1);
                hilo_h(v.z, h2, l2); hilo_h(v.w, h3, l3);
                int cb = xq * 16 + i * 4;
                *(__half2*)(&Xhi[xr][cb])     = __halves2half2(h0, h1);
                *(__half2*)(&Xhi[xr][cb + 2]) = __halves2half2(h2, h3);
                *(__half2*)(&Xlo[xr][cb])     = __halves2half2(l0, l1);
                *(__half2*)(&Xlo[xr][cb + 2]) = __halves2half2(l2, l3);
            }
        }
        {
            const int n0 = tid & 63, kh = tid >> 6;
            const float* src = W + (size_t)(h * EE + k0 + kh * 16) * DK + n0;
            #pragma unroll
            for (int j = 0; j < 8; j++) {
                float va = src[(2 * j) * DK];
                float vb = src[(2 * j + 1) * DK];
                __half ha, hb, la, lb;
                hilo_h(va, ha, la); hilo_h(vb, hb, lb);
                *(__half2*)(&Whi[n0][kh * 16 + 2 * j]) = __halves2half2(ha, hb);
                *(__half2*)(&Wlo[n0][kh * 16 + 2 * j]) = __halves2half2(la, lb);
            }
        }
        __syncthreads();

        #pragma unroll
        for (int kc = 0; kc < 32; kc += 16) {
            uint32_t ahi[4], alo[4];
            ahi[0] = *(const uint32_t*)(&Xhi[row0][kc + 2 * t]);
            ahi[1] = *(const uint32_t*)(&Xhi[row1][kc + 2 * t]);
            ahi[2] = *(const uint32_t*)(&Xhi[row0][kc + 8 + 2 * t]);
            ahi[3] = *(const uint32_t*)(&Xhi[row1][kc + 8 + 2 * t]);
            alo[0] = *(const uint32_t*)(&Xlo[row0][kc + 2 * t]);
            alo[1] = *(const uint32_t*)(&Xlo[row1][kc + 2 * t]);
            alo[2] = *(const uint32_t*)(&Xlo[row0][kc + 8 + 2 * t]);
            alo[3] = *(const uint32_t*)(&Xlo[row1][kc + 8 + 2 * t]);
            #pragma unroll
            for (int nf = 0; nf < 8; nf++) {
                uint32_t bh0 = *(const uint32_t*)(&Whi[nf * 8 + g][kc + 2 * t]);
                uint32_t bh1 = *(const uint32_t*)(&Whi[nf * 8 + g][kc + 8 + 2 * t]);
                uint32_t bl0 = *(const uint32_t*)(&Wlo[nf * 8 + g][kc + 2 * t]);
                uint32_t bl1 = *(const uint32_t*)(&Wlo[nf * 8 + g][kc + 8 + 2 * t]);
                mma_f16(c[nf], ahi, bh0, bh1);
                mma_f16(c[nf], ahi, bl0, bl1);
                mma_f16(c[nf], alo, bh0, bh1);
            }
        }
        __syncthreads();
    }

    if (mat < 2) {
        __half* outp = (mat == 0) ? g_Qh : g_Kh;
        const float sc = (mat == 0) ? 0.125f : 1.0f;
        {
            int m = m0 + row0;
            int b = m >> 11, n = m & (NN - 1);
            __half* dst = outp + ((size_t)(b * HH + h) * NN + n) * DK;
            #pragma unroll
            for (int nf = 0; nf < 8; nf++)
                *(__half2*)(dst + nf * 8 + 2 * t) =
                    __floats2half2_rn(c[nf][0] * sc, c[nf][1] * sc);
        }
        {
            int m = m0 + row1;
            int b = m >> 11, n = m & (NN - 1);
            __half* dst = outp + ((size_t)(b * HH + h) * NN + n) * DK;
            #pragma unroll
            for (int nf = 0; nf < 8; nf++)
                *(__half2*)(dst + nf * 8 + 2 * t) =
                    __floats2half2_rn(c[nf][2] * sc, c[nf][3] * sc);
        }
    } else {
        // V: transpose in SMEM, then write coalesced rows of g_Vt[bh][d][n]
        __syncthreads();
        #pragma unroll
        for (int nf = 0; nf < 8; nf++) {
            int d0 = nf * 8 + 2 * t;
            Vsm[(d0    ) * 72 + row0] = __float2half_rn(c[nf][0]);
            Vsm[(d0 + 1) * 72 + row0] = __float2half_rn(c[nf][1]);
            Vsm[(d0    ) * 72 + row1] = __float2half_rn(c[nf][2]);
            Vsm[(d0 + 1) * 72 + row1] = __float2half_rn(c[nf][3]);
        }
        __syncthreads();
        const int b = m0 >> 11, n0 = m0 & (NN - 1);
        const int d = tid >> 1, part = tid & 1;
        __half* dst = g_Vt + ((size_t)(b * HH + h) * DK + d) * NN + n0 + part * 32;
        const __half* src = &Vsm[d * 72 + part * 32];
        #pragma unroll
        for (int i = 0; i < 4; i++)
            *(uint4*)(dst + i * 8) = *(const uint4*)(src + i * 8);
    }
}

// ===========================================================================
// Kernel 2: flash attention, full fp16 m16n8k16, cp.async double-buffered.
// grid = (16, 8), 256 threads. Zero shuffles in the PV path.
// ===========================================================================
__global__ void __launch_bounds__(256) flash_mma_kernel() {
    __shared__ __half Ks[2][BN][72];      // [buf][key][d]
    __shared__ __half Vs[2][BN][72];      // [buf][d][key]  (from g_Vt)
    __shared__ uint32_t adjm[2][QM][2];

    const int tid = threadIdx.x;
    const int wid = tid >> 5;
    const int lane = tid & 31;
    const int g = lane >> 2;
    const int t = lane & 3;
    const int bh = blockIdx.y;
    const int b  = bh >> 2;
    const int q0 = blockIdx.x * QM;

    const int row0 = wid * 16 + g;
    const int row1 = row0 + 8;

    // staging roles
    const int krow = tid >> 2, kq = tid & 3;     // K: key row / Vt: d row
    const int arow = tid >> 1, ahalf = tid & 1;
    const __half* Kg0 = g_Kh + ((size_t)bh * NN + krow) * DK + kq * 16;
    const __half* Vg0 = g_Vt + ((size_t)bh * DK + krow) * NN + kq * 16;
    const uint32_t* adjp_base = g_adjp + ((size_t)b * NN + q0 + arow) * (NN / 32) + ahalf;

    // preload Q fragments (fp16, pre-scaled)
    uint32_t qa[4][4];
    {
        const __half* Q0 = g_Qh + ((size_t)bh * NN + q0 + row0) * DK;
        const __half* Q1 = g_Qh + ((size_t)bh * NN + q0 + row1) * DK;
        #pragma unroll
        for (int kc = 0; kc < 4; kc++) {
            qa[kc][0] = *(const uint32_t*)(Q0 + kc * 16 + 2 * t);
            qa[kc][1] = *(const uint32_t*)(Q1 + kc * 16 + 2 * t);
            qa[kc][2] = *(const uint32_t*)(Q0 + kc * 16 + 2 * t + 8);
            qa[kc][3] = *(const uint32_t*)(Q1 + kc * 16 + 2 * t + 8);
        }
    }

    float oacc[8][4] = {};
    float m0r = -1e30f, m1r = -1e30f, l0r = 0.f, l1r = 0.f;

    // prefetch tile 0 into buffer 0
    {
        uint32_t kd = smem_u32(&Ks[0][krow][kq * 16]);
        uint32_t vd = smem_u32(&Vs[0][krow][kq * 16]);
        cp16(kd, Kg0);       cp16(kd + 16, Kg0 + 8);
        cp16(vd, Vg0);       cp16(vd + 16, Vg0 + 8);
        cp4(smem_u32(&adjm[0][arow][ahalf]), adjp_base);
        CP_COMMIT();
    }

    for (int tile = 0; tile < NT; tile++) {
        const int buf = tile & 1;
        const int nbuf = buf ^ 1;

        if (tile + 1 < NT) {
            const __half* Kg = Kg0 + (size_t)(tile + 1) * BN * DK;
            const __half* Vg = Vg0 + (tile + 1) * BN;
            uint32_t kd = smem_u32(&Ks[nbuf][krow][kq * 16]);
            uint32_t vd = smem_u32(&Vs[nbuf][krow][kq * 16]);
            cp16(kd, Kg);       cp16(kd + 16, Kg + 8);
            cp16(vd, Vg);       cp16(vd + 16, Vg + 8);
            cp4(smem_u32(&adjm[nbuf][arow][ahalf]), adjp_base + (size_t)(tile + 1) * 2);
            CP_COMMIT();
            CP_WAIT(1);
        } else {
            CP_WAIT(0);
        }
        __syncthreads();

        // ---- S = Q K^T  (fp16 m16n8k16, 32 MMAs) ----
        float sacc[8][4] = {};
        #pragma unroll
        for (int nf = 0; nf < 8; nf++) {
            #pragma unroll
            for (int kc = 0; kc < 4; kc++) {
                uint32_t b0 = *(const uint32_t*)(&Ks[buf][nf * 8 + g][kc * 16 + 2 * t]);
                uint32_t b1 = *(const uint32_t*)(&Ks[buf][nf * 8 + g][kc * 16 + 2 * t + 8]);
                mma_f16(sacc[nf], qa[kc], b0, b1);
            }
        }

        // ---- masked online softmax (f32) ----
        uint32_t w0lo = adjm[buf][row0][0], w0hi = adjm[buf][row0][1];
        uint32_t w1lo = adjm[buf][row1][0], w1hi = adjm[buf][row1][1];
        float mx0 = -1e30f, mx1 = -1e30f;
        #pragma unroll
        for (int nf = 0; nf < 8; nf++) {
            int ca = nf * 8 + 2 * t, cb = ca + 1;
            uint32_t wr0 = (ca < 32) ? w0lo : w0hi;
            uint32_t wr1 = (ca < 32) ? w1lo : w1hi;
            int sa = ca & 31, sb = cb & 31;
            sacc[nf][0] = ((wr0 >> sa) & 1u) ? sacc[nf][0] : -1e38f;
            sacc[nf][1] = ((wr0 >> sb) & 1u) ? sacc[nf][1] : -1e38f;
            sacc[nf][2] = ((wr1 >> sa) & 1u) ? sacc[nf][2] : -1e38f;
            sacc[nf][3] = ((wr1 >> sb) & 1u) ? sacc[nf][3] : -1e38f;
            mx0 = fmaxf(mx0, fmaxf(sacc[nf][0], sacc[nf][1]));
            mx1 = fmaxf(mx1, fmaxf(sacc[nf][2], sacc[nf][3]));
        }
        mx0 = fmaxf(mx0, __shfl_xor_sync(0xffffffffu, mx0, 1));
        mx0 = fmaxf(mx0, __shfl_xor_sync(0xffffffffu, mx0, 2));
        mx1 = fmaxf(mx1, __shfl_xor_sync(0xffffffffu, mx1, 1));
        mx1 = fmaxf(mx1, __shfl_xor_sync(0xffffffffu, mx1, 2));
        float mn0 = fmaxf(m0r, mx0);
        float mn1 = fmaxf(m1r, mx1);
        float s0 = 0.f, s1 = 0.f;
        #pragma unroll
        for (int nf = 0; nf < 8; nf++) {
            float p0 = __expf(sacc[nf][0] - mn0);
            float p1 = __expf(sacc[nf][1] - mn0);
            float p2 = __expf(sacc[nf][2] - mn1);
            float p3 = __expf(sacc[nf][3] - mn1);
            s0 += p0 + p1;
            s1 += p2 + p3;
            sacc[nf][0] = p0; sacc[nf][1] = p1;
            sacc[nf][2] = p2; sacc[nf][3] = p3;
        }
        s0 += __shfl_xor_sync(0xffffffffu, s0, 1);
        s0 += __shfl_xor_sync(0xffffffffu, s0, 2);
        s1 += __shfl_xor_sync(0xffffffffu, s1, 1);
        s1 += __shfl_xor_sync(0xffffffffu, s1, 2);
        float cf0 = __expf(m0r - mn0);
        float cf1 = __expf(m1r - mn1);
        l0r = l0r * cf0 + s0;  m0r = mn0;
        l1r = l1r * cf1 + s1;  m1r = mn1;
        #pragma unroll
        for (int nf = 0; nf < 8; nf++) {
            oacc[nf][0] *= cf0; oacc[nf][1] *= cf0;
            oacc[nf][2] *= cf1; oacc[nf][3] *= cf1;
        }

        // ---- O += P V : C-fragment IS the fp16 A-fragment (no shuffles) ----
        #pragma unroll
        for (int kc = 0; kc < 4; kc++) {
            uint32_t pa[4];
            pa[0] = f22h(sacc[2 * kc][0],     sacc[2 * kc][1]);
            pa[1] = f22h(sacc[2 * kc][2],     sacc[2 * kc][3]);
            pa[2] = f22h(sacc[2 * kc + 1][0], sacc[2 * kc + 1][1]);
            pa[3] = f22h(sacc[2 * kc + 1][2], sacc[2 * kc + 1][3]);
            #pragma unroll
            for (int nf = 0; nf < 8; nf++) {
                uint32_t b0 = *(const uint32_t*)(&Vs[buf][nf * 8 + g][kc * 16 + 2 * t]);
                uint32_t b1 = *(const uint32_t*)(&Vs[buf][nf * 8 + g][kc * 16 + 2 * t + 8]);
                mma_f16(oacc[nf], pa, b0, b1);
            }
        }
        __syncthreads();
    }

    // ---- epilogue ----
    const int h = bh & 3;
    float inv0 = (l0r > 0.f) ? 1.f / l0r : 0.f;
    float inv1 = (l1r > 0.f) ? 1.f / l1r : 0.f;
    float* d0 = g_Hc + ((size_t)(b * NN + q0 + row0)) * EE + h * DK;
    float* d1 = g_Hc + ((size_t)(b * NN + q0 + row1)) * EE + h * DK;
    #pragma unroll
    for (int nf = 0; nf < 8; nf++) {
        int c = nf * 8 + 2 * t;
        float2 w0 = {oacc[nf][0] * inv0, oacc[nf][1] * inv0};
        float2 w1 = {oacc[nf][2] * inv1, oacc[nf][3] * inv1};
        *(float2*)(d0 + c) = w0;
        *(float2*)(d1 + c) = w1;
    }
}

// ===========================================================================
// Kernel 3: out = Hc @ Wo^T + bo, fp16-split 3xHMMA.
// grid = (32, 4), 256 threads, 128-row tiles.
// ===========================================================================
__global__ void __launch_bounds__(256) out_mma_kernel(const float* __restrict__ Wo,
                                                      const float* __restrict__ bo,
                                                      float* __restrict__ out) {
    __shared__ __half Xhi[128][40], Xlo[128][40];
    __shared__ __half Whi[64][40], Wlo[64][40];   // n-major: [n][k]

    const int m0 = blockIdx.x * 128;
    const int c0 = blockIdx.y * 64;
    const int tid = threadIdx.x;
    const int wid = tid >> 5;
    const int lane = tid & 31;
    const int g = lane >> 2, t = lane & 3;
    const int row0 = wid * 16 + g, row1 = row0 + 8;

    float c[8][4] = {};

    for (int k0 = 0; k0 < EE; k0 += 32) {
        {   // stage Hc [128 m x 32 k]
            const int xr = tid >> 1, xq = tid & 1;
            const float4* src = (const float4*)(g_Hc + (size_t)(m0 + xr) * EE + k0 + xq * 16);
            #pragma unroll
            for (int i = 0; i < 4; i++) {
                float4 v = src[i];
                __half h0, h1, h2, h3, l0, l1, l2, l3;
                hilo_h(v.x, h0, l0); hilo_h(v.y, h1, l1);
                hilo_h(v.z, h2, l2); hilo_h(v.w, h3, l3);
                int cb = xq * 16 + i * 4;
                *(__half2*)(&Xhi[xr][cb])     = __halves2half2(h0, h1);
                *(__half2*)(&Xhi[xr][cb + 2]) = __halves2half2(h2, h3);
                *(__half2*)(&Xlo[xr][cb])     = __halves2half2(l0, l1);
                *(__half2*)(&Xlo[xr][cb + 2]) = __halves2half2(l2, l3);
            }
        }
        {   // stage Wo [64 n x 32 k]
            const int nr = tid >> 2, nq = tid & 3;
            const float4* src = (const float4*)(Wo + (size_t)(c0 + nr) * EE + k0 + nq * 8);
            #pragma unroll
            for (int i = 0; i < 2; i++) {
                float4 v = src[i];
                __half h0, h1, h2, h3, l0, l1, l2, l3;
                hilo_h(v.x, h0, l0); hilo_h(v.y, h1, l1);
                hilo_h(v.z, h2, l2); hilo_h(v.w, h3, l3);
                int cb = nq * 8 + i * 4;
                *(__half2*)(&Whi[nr][cb])     = __halves2half2(h0, h1);
                *(__half2*)(&Whi[nr][cb + 2]) = __halves2half2(h2, h3);
                *(__half2*)(&Wlo[nr][cb])     = __halves2half2(l0, l1);
                *(__half2*)(&Wlo[nr][cb + 2]) = __halves2half2(l2, l3);
            }
        }
        __syncthreads();

        #pragma unroll
        for (int kc = 0; kc < 32; kc += 16) {
            uint32_t ahi[4], alo[4];
            ahi[0] = *(const uint32_t*)(&Xhi[row0][kc + 2 * t]);
            ahi[1] = *(const uint32_t*)(&Xhi[row1][kc + 2 * t]);
            ahi[2] = *(const uint32_t*)(&Xhi[row0][kc + 8 + 2 * t]);
            ahi[3] = *(const uint32_t*)(&Xhi[row1][kc + 8 + 2 * t]);
            alo[0] = *(const uint32_t*)(&Xlo[row0][kc + 2 * t]);
            alo[1] = *(const uint32_t*)(&Xlo[row1][kc + 2 * t]);
            alo[2] = *(const uint32_t*)(&Xlo[row0][kc + 8 + 2 * t]);
            alo[3] = *(const uint32_t*)(&Xlo[row1][kc + 8 + 2 * t]);
            #pragma unroll
            for (int nf = 0; nf < 8; nf++) {
                uint32_t bh0 = *(const uint32_t*)(&Whi[nf * 8 + g][kc + 2 * t]);
                uint32_t bh1 = *(const uint32_t*)(&Whi[nf * 8 + g][kc + 8 + 2 * t]);
                uint32_t bl0 = *(const uint32_t*)(&Wlo[nf * 8 + g][kc + 2 * t]);
                uint32_t bl1 = *(const uint32_t*)(&Wlo[nf * 8 + g][kc + 8 + 2 * t]);
                mma_f16(c[nf], ahi, bh0, bh1);
                mma_f16(c[nf], ahi, bl0, bl1);
                mma_f16(c[nf], alo, bh0, bh1);
            }
        }
        __syncthreads();
    }

    #pragma unroll
    for (int nf = 0; nf < 8; nf++) {
        int cc = c0 + nf * 8 + 2 * t;
        float b0v = bo[cc], b1v = bo[cc + 1];
        float2 w0 = {c[nf][0] + b0v, c[nf][1] + b1v};
        float2 w1 = {c[nf][2] + b0v, c[nf][3] + b1v};
        *(float2*)(out + (size_t)(m0 + row0) * EE + cc) = w0;
        *(float2*)(out + (size_t)(m0 + row1) * EE + cc) = w1;
    }
}

extern "C" void kernel_launch(void* const* d_in, const int* in_sizes, int n_in,
                              void* d_out, int out_size) {
    const float* x   = (const float*)d_in[0];
    const int*   adj = (const int*)  d_in[1];
    const float* Wq  = (const float*)d_in[2];
    const float* Wk  = (const float*)d_in[3];
    const float* Wv  = (const float*)d_in[4];
    const float* Wo  = (const float*)d_in[5];
    const float* bo  = (const float*)d_in[6];
    float* out = (float*)d_out;

    pack_adj_kernel<<<(BB * NN * (NN / 32)) / (8 * 32), 256>>>(adj);
    qkv_mma_kernel<<<dim3((BB * NN) / 64, 12), 128>>>(x, Wq, Wk, Wv);
    flash_mma_kernel<<<dim3(NN / QM, BB * HH), 256>>>();
    out_mma_kernel<<<dim3((BB * NN) / 128, EE / 64), 256>>>(Wo, bo, out);
}